// round 15
// baseline (speedup 1.0000x reference)
#include <cuda_runtime.h>
#include <cuda_bf16.h>
#include <math.h>
#include <stdint.h>

// R15: half-dimension fp8 detector (K=256) with rigorous Cauchy-Schwarz/AM-GM
// threshold; exact fp32 fixup unchanged. Gram MACs halved vs R14.

#define B      8192
#define D      512
#define D2     256           // detector dimensions
#define ALPHA  0.5f
#define MARGIN 0.5f
#define NUM_IDS 1024
#define CAP    (1u << 20)
#define MAXG   128
#define BCE_BLOCKS 32

#define TM 128
#define TN 128
#define BK 128               // fp8 elems per stage (128 bytes/row)
#define STAGE_BYTES 32768    // A 16KB + B 16KB
#define SMEM_GRAM (2 * STAGE_BYTES + 1024)
#define PADROWS (66 * 128)
#define TRI_MAX 2080         // tri(64): worst-case tiles per class

// ---------------- scratch ----------------
__device__ uint8_t g_e8p[PADROWS * D2]; // e4m3 first-half copy, partitioned
__device__ float   g_inv[B];
__device__ float   g_sq[B];
__device__ float   g_hp[PADROWS];       // first-half norm^2 permuted (+100 pad)
__device__ int     g_rank[B];
__device__ int     g_perm[PADROWS];
__device__ int     g_T0, g_T1, g_base1;
__device__ float   g_pull[NUM_IDS];
__device__ float   g_bce[BCE_BLOCKS];
__device__ unsigned g_cand[CAP];
__device__ unsigned g_cand_n;

// ---------------- PTX helpers ----------------
__device__ __forceinline__ void cpa16(uint32_t dst, const void* src) {
    asm volatile("cp.async.cg.shared.global [%0], [%1], 16;\n" :: "r"(dst), "l"(src));
}
#define CP_COMMIT() asm volatile("cp.async.commit_group;\n" ::: "memory")
#define CP_WAIT0()  asm volatile("cp.async.wait_group 0;\n" ::: "memory")

__device__ __forceinline__ void ldsm4(uint32_t* r, uint32_t addr) {
    asm volatile("ldmatrix.sync.aligned.m8n8.x4.shared.b16 {%0,%1,%2,%3}, [%4];\n"
                 : "=r"(r[0]), "=r"(r[1]), "=r"(r[2]), "=r"(r[3]) : "r"(addr));
}
__device__ __forceinline__ void mma_fp8(float* d, const uint32_t* a,
                                        uint32_t b0, uint32_t b1) {
    asm volatile(
        "mma.sync.aligned.m16n8k32.row.col.f32.e4m3.e4m3.f32 "
        "{%0,%1,%2,%3}, {%4,%5,%6,%7}, {%8,%9}, {%0,%1,%2,%3};\n"
        : "+f"(d[0]), "+f"(d[1]), "+f"(d[2]), "+f"(d[3])
        : "r"(a[0]), "r"(a[1]), "r"(a[2]), "r"(a[3]), "r"(b0), "r"(b1));
}
__device__ __forceinline__ uint32_t pack_e4m3x4(float x, float y, float z, float w) {
    uint16_t lo, hi;
    asm("cvt.rn.satfinite.e4m3x2.f32 %0, %1, %2;" : "=h"(lo) : "f"(y), "f"(x));
    asm("cvt.rn.satfinite.e4m3x2.f32 %0, %1, %2;" : "=h"(hi) : "f"(w), "f"(z));
    return ((uint32_t)hi << 16) | lo;
}

// ---------------- kernel 0: stable class partition (warp-shuffle scan) -----
__global__ void __launch_bounds__(1024) partition_kernel(const float* __restrict__ classes) {
    __shared__ int warpS[32], warpP[32];
    const int t = threadIdx.x;
    const int lane = t & 31, wid = t >> 5;
    const int base = t * 8;
    int cls[8];
    int c0 = 0;
    #pragma unroll
    for (int k = 0; k < 8; k++) {
        cls[k] = (classes[base + k] == 0.0f) ? 1 : 0;
        c0 += cls[k];
    }
    int x = c0;
    #pragma unroll
    for (int off = 1; off < 32; off <<= 1) {
        int v = __shfl_up_sync(0xffffffff, x, off);
        if (lane >= off) x += v;
    }
    if (lane == 31) warpS[wid] = x;
    __syncthreads();
    if (wid == 0) {
        int y = warpS[lane];
        #pragma unroll
        for (int off = 1; off < 32; off <<= 1) {
            int v = __shfl_up_sync(0xffffffff, y, off);
            if (lane >= off) y += v;
        }
        warpP[lane] = y;
    }
    __syncthreads();
    const int incl = x + (wid ? warpP[wid - 1] : 0);
    const int n0 = warpP[31];
    const int pre0 = incl - c0;
    const int n1 = B - n0;
    const int T0 = (n0 + 127) >> 7;
    const int T1 = (n1 + 127) >> 7;
    const int base1 = T0 * 128;

    int p0 = pre0;
    int p1 = base1 + (base - pre0);
    #pragma unroll
    for (int k = 0; k < 8; k++) {
        int orig = base + k;
        int pos = cls[k] ? p0++ : p1++;
        g_rank[orig] = pos;
        g_perm[pos] = orig;
    }
    if (t == 0) { g_T0 = T0; g_T1 = T1; g_base1 = base1; }

    for (int p = n0 + t; p < base1; p += 1024) {
        g_perm[p] = -1;
        g_hp[p] = 100.0f;
        uint4 z = make_uint4(0, 0, 0, 0);
        #pragma unroll
        for (int q = 0; q < 16; q++)
            ((uint4*)(g_e8p + (size_t)p * D2))[q] = z;
    }
    const int end1 = base1 + T1 * 128;
    for (int p = base1 + n1 + t; p < end1; p += 1024) {
        g_perm[p] = -1;
        g_hp[p] = 100.0f;
        uint4 z = make_uint4(0, 0, 0, 0);
        #pragma unroll
        for (int q = 0; q < 16; q++)
            ((uint4*)(g_e8p + (size_t)p * D2))[q] = z;
    }
}

// ---------------- kernel 1: normalize, 2 rows per block ----------------
// writes fp8 first-half (256 B/row, permuted), g_inv, g_sq, g_hp.
__global__ void __launch_bounds__(256) normalize_kernel(const float* __restrict__ emb) {
    const int t = threadIdx.x;
    const int half = t >> 7;
    const int tt = t & 127;
    const int row = blockIdx.x * 2 + half;
    if (blockIdx.x == 0 && t == 0) g_cand_n = 0u;
    float4 v = ((const float4*)(emb + (size_t)row * D))[tt];
    float s = v.x * v.x + v.y * v.y + v.z * v.z + v.w * v.w;
    #pragma unroll
    for (int o = 16; o > 0; o >>= 1) s += __shfl_down_sync(0xffffffff, s, o);
    __shared__ float sm[8];
    if ((t & 31) == 0) sm[t >> 5] = s;
    __syncthreads();
    const int b4 = half * 4;
    float tot = sm[b4] + sm[b4 + 1] + sm[b4 + 2] + sm[b4 + 3];
    // warp b4 covers dims [0,128), warp b4+1 covers [128,256)
    float hraw = sm[b4] + sm[b4 + 1];
    float inv = 1.0f / fmaxf(sqrtf(tot), 1e-12f);
    float4 o4 = make_float4(v.x * inv, v.y * inv, v.z * inv, v.w * inv);
    int pr = g_rank[row];
    if (tt < 64)  // dims [0,256): fp8 detector copy
        ((uint32_t*)g_e8p)[(size_t)pr * (D2 / 4) + tt] =
            pack_e4m3x4(o4.x, o4.y, o4.z, o4.w);
    if (tt == 0) {
        float sq = tot * inv * inv;
        g_inv[row] = inv;
        g_sq[row] = sq;
        g_hp[pr] = hraw * inv * inv;
    }
}

// ---------------- kernel 2: exact per-id pull term ----------------
__global__ void __launch_bounds__(256) pull_kernel(const float* __restrict__ classes,
                                                   const int* __restrict__ ids,
                                                   const float* __restrict__ emb) {
    int g = blockIdx.x;
    int t = threadIdx.x;
    __shared__ unsigned mask[256];
    __shared__ int   list[MAXG];
    __shared__ float lcls[MAXG];
    __shared__ float linv[MAXG];
    __shared__ int   cnt_s;
    __shared__ float n0s, n1s, sq0s, sq1s;
    __shared__ float red[256];

    mask[t] = 0u;
    __syncthreads();
    #pragma unroll
    for (int it = 0; it < B / 256; it++) {
        int r = t + it * 256;
        if (ids[r] == g) atomicOr(&mask[r >> 5], 1u << (r & 31));
    }
    __syncthreads();
    if (t == 0) {
        int c = 0;
        float n0 = 0.f, n1 = 0.f, s0 = 0.f, s1 = 0.f;
        for (int w = 0; w < 256; w++) {
            unsigned m = mask[w];
            while (m) {
                int b = __ffs(m) - 1;
                m &= m - 1;
                int r = w * 32 + b;
                float cl = classes[r];
                float sq = g_sq[r];
                if (c < MAXG) { list[c] = r; lcls[c] = cl; linv[c] = g_inv[r]; }
                c++;
                if (cl == 0.0f) { n0 += 1.f; s0 += sq; }
                else            { n1 += 1.f; s1 += sq; }
            }
        }
        cnt_s = c; n0s = n0; n1s = n1; sq0s = s0; sq1s = s1;
    }
    __syncthreads();
    int cnt = cnt_s < MAXG ? cnt_s : MAXG;
    float a0 = 0.f, a1 = 0.f, b0 = 0.f, b1 = 0.f;
    for (int k = 0; k < cnt; k++) {
        int r = list[k];
        float cl = lcls[k];
        float iv = linv[k];
        float v0 = emb[(size_t)r * D + t] * iv;
        float v1 = emb[(size_t)r * D + t + 256] * iv;
        if (cl == 0.0f) { a0 += v0; b0 += v1; }
        else            { a1 += v0; b1 += v1; }
    }
    red[t] = a0 * a1 + b0 * b1;
    __syncthreads();
    #pragma unroll
    for (int s = 128; s > 0; s >>= 1) {
        if (t < s) red[t] += red[t + s];
        __syncthreads();
    }
    if (t == 0)
        g_pull[g] = n1s * sq0s + n0s * sq1s - 2.0f * red[0];
}

// ---------------- kernel 3: fp8 half-dim Gram detector (2 K-stages) --------
// Hinge-capable pairs satisfy dot_half1 > 0.5*(h_i+h_j) - 0.25 (Cauchy-Schwarz
// + AM-GM on the second half); fp8 error bound <= 0.08 -> offset -0.38.
__global__ void __launch_bounds__(256, 2) gram_kernel() {
    const int cls = blockIdx.y;
    const int T = cls ? g_T1 : g_T0;
    int k = blockIdx.x;
    int tj = (int)((__fsqrt_rn(8.0f * (float)k + 1.0f) - 1.0f) * 0.5f);
    while ((tj + 1) * (tj + 2) / 2 <= k) ++tj;
    while (tj * (tj + 1) / 2 > k) --tj;
    const int ti = k - tj * (tj + 1) / 2;
    if (tj >= T) return;
    const int pbase = cls ? g_base1 : 0;

    extern __shared__ __align__(1024) unsigned char dsm[];
    uint32_t sRaw = (uint32_t)__cvta_generic_to_shared(dsm);
    uint32_t sBase = (sRaw + 1023u) & ~1023u;

    __shared__ float hI[TM];
    __shared__ float thrJ[TN];

    const int tid = threadIdx.x;
    const int lane = tid & 31, warp = tid >> 5;
    const int wy = warp >> 1, wx = warp & 1;
    const int iBase = pbase + ti * TM, jBase = pbase + tj * TN;

    if (tid < TM) hI[tid] = g_hp[iBase + tid];
    else          thrJ[tid - TM] = 0.5f * g_hp[jBase + tid - TM] - 0.38f;

    float acc[2][8][4];
    #pragma unroll
    for (int m = 0; m < 2; m++)
        #pragma unroll
        for (int n = 0; n < 8; n++)
            #pragma unroll
            for (int r = 0; r < 4; r++) acc[m][n][r] = 0.0f;

    const int ldrow = tid >> 3;
    const int ldgrp = tid & 7;
    const uint32_t dst0 = (uint32_t)(ldrow * 128) +
                          ((uint32_t)(ldgrp ^ (ldrow & 7)) << 4);
    const uint8_t* srcA = g_e8p + (size_t)(iBase + ldrow) * D2 + ldgrp * 16;
    const uint8_t* srcB = g_e8p + (size_t)(jBase + ldrow) * D2 + ldgrp * 16;

    auto loadStage = [&](int s) {
        uint32_t base = sBase + (uint32_t)(s & 1) * STAGE_BYTES + dst0;
        const uint8_t* pa = srcA + s * BK;
        const uint8_t* pb = srcB + s * BK;
        #pragma unroll
        for (int l = 0; l < 4; l++) {
            cpa16(base + l * 4096u, pa + (size_t)l * 8192u);
            cpa16(base + 16384u + l * 4096u, pb + (size_t)l * 8192u);
        }
    };

    const int lrow = lane & 7;
    const int subh = (lane >> 3) & 1;
    const int subg = lane >> 4;
    const int rowA = wy * 32 + lrow + subh * 8;
    const int rowB = wx * 64 + lrow + subh * 8;
    const uint32_t rowA128 = (uint32_t)(rowA * 128);
    const uint32_t rowB128 = 16384u + (uint32_t)(rowB * 128);
    const uint32_t maskA = (uint32_t)(rowA & 7);
    const uint32_t maskB = (uint32_t)(rowB & 7);

    loadStage(0);
    CP_COMMIT();

    #pragma unroll 1
    for (int s = 0; s < D2 / BK; s++) {
        CP_WAIT0();
        __syncthreads();
        if (s + 1 < D2 / BK) {
            loadStage(s + 1);
            CP_COMMIT();
        }

        const uint32_t base = sBase + (uint32_t)(s & 1) * STAGE_BYTES;
        #pragma unroll
        for (int ks = 0; ks < 4; ks++) {
            const uint32_t grp = (uint32_t)(2 * ks + subg);
            const uint32_t offAk = base + rowA128 + ((grp ^ maskA) << 4);
            const uint32_t offBk = base + rowB128 + ((grp ^ maskB) << 4);
            uint32_t a0[4], a1[4];
            ldsm4(a0, offAk);
            ldsm4(a1, offAk + 2048u);
            uint32_t bf[4][4];
            #pragma unroll
            for (int nb = 0; nb < 4; nb++)
                ldsm4(bf[nb], offBk + (uint32_t)nb * 2048u);
            #pragma unroll
            for (int nb = 0; nb < 4; nb++) {
                mma_fp8(acc[0][2 * nb],     a0, bf[nb][0], bf[nb][2]);
                mma_fp8(acc[0][2 * nb + 1], a0, bf[nb][1], bf[nb][3]);
                mma_fp8(acc[1][2 * nb],     a1, bf[nb][0], bf[nb][2]);
                mma_fp8(acc[1][2 * nb + 1], a1, bf[nb][1], bf[nb][3]);
            }
        }
    }

    // epilogue: flag dot_half1_fp8 > 0.5*(h_i+h_j) - 0.38 (permuted positions)
    const bool diag = (ti == tj);
    const int g = lane >> 2, t4 = lane & 3;
    #pragma unroll
    for (int ma = 0; ma < 2; ma++)
        #pragma unroll
        for (int nf = 0; nf < 8; nf++)
            #pragma unroll
            for (int r = 0; r < 4; r++) {
                float v = acc[ma][nf][r];
                float thr = 0.5f * hI[wy * 32 + ma * 16 + g + (r >> 1) * 8] +
                            thrJ[wx * 64 + nf * 8 + t4 * 2 + (r & 1)];
                if (v > thr) {
                    int pi = iBase + wy * 32 + ma * 16 + g + (r >> 1) * 8;
                    int pj = jBase + wx * 64 + nf * 8 + t4 * 2 + (r & 1);
                    if (!diag || pj > pi) {
                        unsigned pos = atomicAdd(&g_cand_n, 1u);
                        if (pos < CAP)
                            g_cand[pos] = ((unsigned)pi << 14) | (unsigned)pj;
                    }
                }
            }
}

// ---------------- kernel 4: BCE partials (overlapped on side stream) -------
__global__ void bce_kernel(const float* __restrict__ outputs,
                           const float* __restrict__ classes) {
    float s = 0.0f;
    for (int i = blockIdx.x * blockDim.x + threadIdx.x; i < B;
         i += gridDim.x * blockDim.x) {
        float o = outputs[i], cl = classes[i];
        s += fmaxf(o, 0.0f) - o * cl + log1pf(expf(-fabsf(o)));
    }
    __shared__ float red[256];
    red[threadIdx.x] = s;
    __syncthreads();
    #pragma unroll
    for (int k = 128; k > 0; k >>= 1) {
        if (threadIdx.x < k) red[threadIdx.x] += red[threadIdx.x + k];
        __syncthreads();
    }
    if (threadIdx.x == 0) g_bce[blockIdx.x] = red[0];
}

// ---------------- kernel 5: fixup + final deterministic reduce -------------
__global__ void final_kernel(const float* __restrict__ classes,
                             const int* __restrict__ ids,
                             const float* __restrict__ emb,
                             float* __restrict__ out) {
    const int t = threadIdx.x;  // 256
    const int lane = t & 31, warp = t >> 5;
    __shared__ float redP[256];
    __shared__ float sh_hinge;
    if (t == 0) sh_hinge = 0.0f;
    __syncthreads();

    // exact full-D fp32 fixup of flagged pairs
    unsigned n = g_cand_n;
    if (n > CAP) n = CAP;
    for (unsigned c = warp; c < n; c += 8) {
        unsigned pk = g_cand[c];
        int pi = pk >> 14, pj = pk & 16383;
        int i = g_perm[pi], j = g_perm[pj];
        if (i < 0 || j < 0) continue;
        float inv_i = g_inv[i], inv_j = g_inv[j];
        float s = 0.0f;
        #pragma unroll 4
        for (int kk = lane; kk < D; kk += 32) {
            float a = emb[(size_t)i * D + kk] * inv_i;
            float b = emb[(size_t)j * D + kk] * inv_j;
            s += a * b;
        }
        #pragma unroll
        for (int o = 16; o > 0; o >>= 1) s += __shfl_down_sync(0xffffffff, s, o);
        if (lane == 0) {
            if (ids[i] != ids[j] && classes[i] == classes[j]) {
                float d2 = fmaxf(g_sq[i] + g_sq[j] - 2.0f * s, 0.0f);
                float term = fmaxf(0.0f, MARGIN - d2);
                if (term > 0.0f) atomicAdd(&sh_hinge, term);
            }
        }
    }

    float sp = 0.0f;
    for (int i = t; i < NUM_IDS; i += 256) sp += g_pull[i];
    redP[t] = sp;
    __syncthreads();
    #pragma unroll
    for (int k = 128; k > 0; k >>= 1) {
        if (t < k) redP[t] += redP[t + k];
        __syncthreads();
    }
    if (t == 0) {
        float bsum = 0.0f;
        #pragma unroll
        for (int i = 0; i < BCE_BLOCKS; i++) bsum += g_bce[i];
        float l = 0.5f * redP[0] + sh_hinge;
        out[0] = bsum / (float)B + ALPHA * l;
    }
}

// ---------------------------------------------------------------------------
extern "C" void kernel_launch(void* const* d_in, const int* in_sizes, int n_in,
                              void* d_out, int out_size) {
    const float* outputs = (const float*)d_in[0];
    const float* classes = (const float*)d_in[1];
    const float* emb     = (const float*)d_in[2];
    const int*   ids     = (const int*)d_in[3];
    float* out = (float*)d_out;

    static cudaStream_t s1 = nullptr;
    static cudaEvent_t ev0 = nullptr, evA = nullptr, evB = nullptr;
    if (s1 == nullptr) {
        cudaStreamCreateWithFlags(&s1, cudaStreamNonBlocking);
        cudaEventCreateWithFlags(&ev0, cudaEventDisableTiming);
        cudaEventCreateWithFlags(&evA, cudaEventDisableTiming);
        cudaEventCreateWithFlags(&evB, cudaEventDisableTiming);
        cudaFuncSetAttribute(gram_kernel,
                             cudaFuncAttributeMaxDynamicSharedMemorySize,
                             SMEM_GRAM);
    }

    // fork immediately: BCE depends only on inputs
    cudaEventRecord(ev0, 0);
    cudaStreamWaitEvent(s1, ev0, 0);
    bce_kernel<<<BCE_BLOCKS, 256, 0, s1>>>(outputs, classes);

    partition_kernel<<<1, 1024>>>(classes);
    normalize_kernel<<<B / 2, 256>>>(emb);

    // pull on s1 (needs normalize results), concurrent with gram
    cudaEventRecord(evA, 0);
    cudaStreamWaitEvent(s1, evA, 0);
    pull_kernel<<<NUM_IDS, 256, 0, s1>>>(classes, ids, emb);
    cudaEventRecord(evB, s1);

    gram_kernel<<<dim3(TRI_MAX, 2), 256, SMEM_GRAM>>>();

    cudaStreamWaitEvent(0, evB, 0);
    final_kernel<<<1, 256>>>(classes, ids, emb, out);
}

// round 16
// speedup vs baseline: 18.5443x; 18.5443x over previous
#include <cuda_runtime.h>
#include <cuda_bf16.h>
#include <math.h>
#include <stdint.h>

// R16: half-dim fp8 detector with h-aware rigorous threshold
// (0.4375*(h_i+h_j) - 0.285) and PARALLEL 64-block exact fixup.
// R15 failed on candidate-tail smearing + single-block fixup serialization.

#define B      8192
#define D      512
#define D2     256           // detector dimensions
#define ALPHA  0.5f
#define MARGIN 0.5f
#define NUM_IDS 1024
#define CAP    (1u << 20)
#define MAXG   128
#define BCE_BLOCKS 32

#define TM 128
#define TN 128
#define BK 128               // fp8 elems per stage (128 bytes/row)
#define STAGE_BYTES 32768    // A 16KB + B 16KB
#define SMEM_GRAM (2 * STAGE_BYTES + 1024)
#define PADROWS (66 * 128)
#define TRI_MAX 2080         // tri(64): worst-case tiles per class

// ---------------- scratch ----------------
__device__ uint8_t g_e8p[PADROWS * D2]; // e4m3 first-half copy, partitioned
__device__ float   g_inv[B];
__device__ float   g_sq[B];
__device__ float   g_hp[PADROWS];       // first-half norm^2 permuted (+100 pad)
__device__ int     g_rank[B];
__device__ int     g_perm[PADROWS];
__device__ int     g_T0, g_T1, g_base1;
__device__ float   g_pull[NUM_IDS];
__device__ float   g_bce[BCE_BLOCKS];
__device__ unsigned g_cand[CAP];
__device__ unsigned g_cand_n;
__device__ float   g_hinge;

// ---------------- PTX helpers ----------------
__device__ __forceinline__ void cpa16(uint32_t dst, const void* src) {
    asm volatile("cp.async.cg.shared.global [%0], [%1], 16;\n" :: "r"(dst), "l"(src));
}
#define CP_COMMIT() asm volatile("cp.async.commit_group;\n" ::: "memory")
#define CP_WAIT0()  asm volatile("cp.async.wait_group 0;\n" ::: "memory")

__device__ __forceinline__ void ldsm4(uint32_t* r, uint32_t addr) {
    asm volatile("ldmatrix.sync.aligned.m8n8.x4.shared.b16 {%0,%1,%2,%3}, [%4];\n"
                 : "=r"(r[0]), "=r"(r[1]), "=r"(r[2]), "=r"(r[3]) : "r"(addr));
}
__device__ __forceinline__ void mma_fp8(float* d, const uint32_t* a,
                                        uint32_t b0, uint32_t b1) {
    asm volatile(
        "mma.sync.aligned.m16n8k32.row.col.f32.e4m3.e4m3.f32 "
        "{%0,%1,%2,%3}, {%4,%5,%6,%7}, {%8,%9}, {%0,%1,%2,%3};\n"
        : "+f"(d[0]), "+f"(d[1]), "+f"(d[2]), "+f"(d[3])
        : "r"(a[0]), "r"(a[1]), "r"(a[2]), "r"(a[3]), "r"(b0), "r"(b1));
}
__device__ __forceinline__ uint32_t pack_e4m3x4(float x, float y, float z, float w) {
    uint16_t lo, hi;
    asm("cvt.rn.satfinite.e4m3x2.f32 %0, %1, %2;" : "=h"(lo) : "f"(y), "f"(x));
    asm("cvt.rn.satfinite.e4m3x2.f32 %0, %1, %2;" : "=h"(hi) : "f"(w), "f"(z));
    return ((uint32_t)hi << 16) | lo;
}

// ---------------- kernel 0: stable class partition (warp-shuffle scan) -----
__global__ void __launch_bounds__(1024) partition_kernel(const float* __restrict__ classes) {
    __shared__ int warpS[32], warpP[32];
    const int t = threadIdx.x;
    const int lane = t & 31, wid = t >> 5;
    const int base = t * 8;
    int cls[8];
    int c0 = 0;
    #pragma unroll
    for (int k = 0; k < 8; k++) {
        cls[k] = (classes[base + k] == 0.0f) ? 1 : 0;
        c0 += cls[k];
    }
    int x = c0;
    #pragma unroll
    for (int off = 1; off < 32; off <<= 1) {
        int v = __shfl_up_sync(0xffffffff, x, off);
        if (lane >= off) x += v;
    }
    if (lane == 31) warpS[wid] = x;
    __syncthreads();
    if (wid == 0) {
        int y = warpS[lane];
        #pragma unroll
        for (int off = 1; off < 32; off <<= 1) {
            int v = __shfl_up_sync(0xffffffff, y, off);
            if (lane >= off) y += v;
        }
        warpP[lane] = y;
    }
    __syncthreads();
    const int incl = x + (wid ? warpP[wid - 1] : 0);
    const int n0 = warpP[31];
    const int pre0 = incl - c0;
    const int n1 = B - n0;
    const int T0 = (n0 + 127) >> 7;
    const int T1 = (n1 + 127) >> 7;
    const int base1 = T0 * 128;

    int p0 = pre0;
    int p1 = base1 + (base - pre0);
    #pragma unroll
    for (int k = 0; k < 8; k++) {
        int orig = base + k;
        int pos = cls[k] ? p0++ : p1++;
        g_rank[orig] = pos;
        g_perm[pos] = orig;
    }
    if (t == 0) { g_T0 = T0; g_T1 = T1; g_base1 = base1; }

    for (int p = n0 + t; p < base1; p += 1024) {
        g_perm[p] = -1;
        g_hp[p] = 100.0f;
        uint4 z = make_uint4(0, 0, 0, 0);
        #pragma unroll
        for (int q = 0; q < 16; q++)
            ((uint4*)(g_e8p + (size_t)p * D2))[q] = z;
    }
    const int end1 = base1 + T1 * 128;
    for (int p = base1 + n1 + t; p < end1; p += 1024) {
        g_perm[p] = -1;
        g_hp[p] = 100.0f;
        uint4 z = make_uint4(0, 0, 0, 0);
        #pragma unroll
        for (int q = 0; q < 16; q++)
            ((uint4*)(g_e8p + (size_t)p * D2))[q] = z;
    }
}

// ---------------- kernel 1: normalize, 2 rows per block ----------------
__global__ void __launch_bounds__(256) normalize_kernel(const float* __restrict__ emb) {
    const int t = threadIdx.x;
    const int half = t >> 7;
    const int tt = t & 127;
    const int row = blockIdx.x * 2 + half;
    if (blockIdx.x == 0 && t == 0) { g_cand_n = 0u; g_hinge = 0.0f; }
    float4 v = ((const float4*)(emb + (size_t)row * D))[tt];
    float s = v.x * v.x + v.y * v.y + v.z * v.z + v.w * v.w;
    #pragma unroll
    for (int o = 16; o > 0; o >>= 1) s += __shfl_down_sync(0xffffffff, s, o);
    __shared__ float sm[8];
    if ((t & 31) == 0) sm[t >> 5] = s;
    __syncthreads();
    const int b4 = half * 4;
    float tot = sm[b4] + sm[b4 + 1] + sm[b4 + 2] + sm[b4 + 3];
    float hraw = sm[b4] + sm[b4 + 1];   // dims [0,256) of this row
    float inv = 1.0f / fmaxf(sqrtf(tot), 1e-12f);
    float4 o4 = make_float4(v.x * inv, v.y * inv, v.z * inv, v.w * inv);
    int pr = g_rank[row];
    if (tt < 64)
        ((uint32_t*)g_e8p)[(size_t)pr * (D2 / 4) + tt] =
            pack_e4m3x4(o4.x, o4.y, o4.z, o4.w);
    if (tt == 0) {
        float sq = tot * inv * inv;
        g_inv[row] = inv;
        g_sq[row] = sq;
        g_hp[pr] = hraw * inv * inv;
    }
}

// ---------------- kernel 2: exact per-id pull term ----------------
__global__ void __launch_bounds__(256) pull_kernel(const float* __restrict__ classes,
                                                   const int* __restrict__ ids,
                                                   const float* __restrict__ emb) {
    int g = blockIdx.x;
    int t = threadIdx.x;
    __shared__ unsigned mask[256];
    __shared__ int   list[MAXG];
    __shared__ float lcls[MAXG];
    __shared__ float linv[MAXG];
    __shared__ int   cnt_s;
    __shared__ float n0s, n1s, sq0s, sq1s;
    __shared__ float red[256];

    mask[t] = 0u;
    __syncthreads();
    #pragma unroll
    for (int it = 0; it < B / 256; it++) {
        int r = t + it * 256;
        if (ids[r] == g) atomicOr(&mask[r >> 5], 1u << (r & 31));
    }
    __syncthreads();
    if (t == 0) {
        int c = 0;
        float n0 = 0.f, n1 = 0.f, s0 = 0.f, s1 = 0.f;
        for (int w = 0; w < 256; w++) {
            unsigned m = mask[w];
            while (m) {
                int b = __ffs(m) - 1;
                m &= m - 1;
                int r = w * 32 + b;
                float cl = classes[r];
                float sq = g_sq[r];
                if (c < MAXG) { list[c] = r; lcls[c] = cl; linv[c] = g_inv[r]; }
                c++;
                if (cl == 0.0f) { n0 += 1.f; s0 += sq; }
                else            { n1 += 1.f; s1 += sq; }
            }
        }
        cnt_s = c; n0s = n0; n1s = n1; sq0s = s0; sq1s = s1;
    }
    __syncthreads();
    int cnt = cnt_s < MAXG ? cnt_s : MAXG;
    float a0 = 0.f, a1 = 0.f, b0 = 0.f, b1 = 0.f;
    for (int k = 0; k < cnt; k++) {
        int r = list[k];
        float cl = lcls[k];
        float iv = linv[k];
        float v0 = emb[(size_t)r * D + t] * iv;
        float v1 = emb[(size_t)r * D + t + 256] * iv;
        if (cl == 0.0f) { a0 += v0; b0 += v1; }
        else            { a1 += v0; b1 += v1; }
    }
    red[t] = a0 * a1 + b0 * b1;
    __syncthreads();
    #pragma unroll
    for (int s = 128; s > 0; s >>= 1) {
        if (t < s) red[t] += red[t + s];
        __syncthreads();
    }
    if (t == 0)
        g_pull[g] = n1s * sq0s + n0s * sq1s - 2.0f * red[0];
}

// ---------------- kernel 3: fp8 half-dim Gram detector (2 K-stages) --------
// Hinge-capable pairs satisfy dot_half1_true > 0.5*(h_i+h_j) - 0.25
// (Cauchy-Schwarz + AM-GM on the second half). fp8 error:
//   |dot_fp8 - dot_true| <= 0.125*sqrt(h_i h_j) + 0.035
//                        <= 0.0625*(h_i+h_j) + 0.035.
// => flag if dot_fp8 > 0.4375*(h_i+h_j) - 0.285  (rigorous superset).
__global__ void __launch_bounds__(256, 2) gram_kernel() {
    const int cls = blockIdx.y;
    const int T = cls ? g_T1 : g_T0;
    int k = blockIdx.x;
    int tj = (int)((__fsqrt_rn(8.0f * (float)k + 1.0f) - 1.0f) * 0.5f);
    while ((tj + 1) * (tj + 2) / 2 <= k) ++tj;
    while (tj * (tj + 1) / 2 > k) --tj;
    const int ti = k - tj * (tj + 1) / 2;
    if (tj >= T) return;
    const int pbase = cls ? g_base1 : 0;

    extern __shared__ __align__(1024) unsigned char dsm[];
    uint32_t sRaw = (uint32_t)__cvta_generic_to_shared(dsm);
    uint32_t sBase = (sRaw + 1023u) & ~1023u;

    __shared__ float hI[TM];
    __shared__ float thrJ[TN];

    const int tid = threadIdx.x;
    const int lane = tid & 31, warp = tid >> 5;
    const int wy = warp >> 1, wx = warp & 1;
    const int iBase = pbase + ti * TM, jBase = pbase + tj * TN;

    if (tid < TM) hI[tid] = 0.4375f * g_hp[iBase + tid];
    else          thrJ[tid - TM] = 0.4375f * g_hp[jBase + tid - TM] - 0.285f;

    float acc[2][8][4];
    #pragma unroll
    for (int m = 0; m < 2; m++)
        #pragma unroll
        for (int n = 0; n < 8; n++)
            #pragma unroll
            for (int r = 0; r < 4; r++) acc[m][n][r] = 0.0f;

    const int ldrow = tid >> 3;
    const int ldgrp = tid & 7;
    const uint32_t dst0 = (uint32_t)(ldrow * 128) +
                          ((uint32_t)(ldgrp ^ (ldrow & 7)) << 4);
    const uint8_t* srcA = g_e8p + (size_t)(iBase + ldrow) * D2 + ldgrp * 16;
    const uint8_t* srcB = g_e8p + (size_t)(jBase + ldrow) * D2 + ldgrp * 16;

    auto loadStage = [&](int s) {
        uint32_t base = sBase + (uint32_t)(s & 1) * STAGE_BYTES + dst0;
        const uint8_t* pa = srcA + s * BK;
        const uint8_t* pb = srcB + s * BK;
        #pragma unroll
        for (int l = 0; l < 4; l++) {
            cpa16(base + l * 4096u, pa + (size_t)l * 8192u);
            cpa16(base + 16384u + l * 4096u, pb + (size_t)l * 8192u);
        }
    };

    const int lrow = lane & 7;
    const int subh = (lane >> 3) & 1;
    const int subg = lane >> 4;
    const int rowA = wy * 32 + lrow + subh * 8;
    const int rowB = wx * 64 + lrow + subh * 8;
    const uint32_t rowA128 = (uint32_t)(rowA * 128);
    const uint32_t rowB128 = 16384u + (uint32_t)(rowB * 128);
    const uint32_t maskA = (uint32_t)(rowA & 7);
    const uint32_t maskB = (uint32_t)(rowB & 7);

    loadStage(0);
    CP_COMMIT();

    #pragma unroll 1
    for (int s = 0; s < D2 / BK; s++) {
        CP_WAIT0();
        __syncthreads();
        if (s + 1 < D2 / BK) {
            loadStage(s + 1);
            CP_COMMIT();
        }

        const uint32_t base = sBase + (uint32_t)(s & 1) * STAGE_BYTES;
        #pragma unroll
        for (int ks = 0; ks < 4; ks++) {
            const uint32_t grp = (uint32_t)(2 * ks + subg);
            const uint32_t offAk = base + rowA128 + ((grp ^ maskA) << 4);
            const uint32_t offBk = base + rowB128 + ((grp ^ maskB) << 4);
            uint32_t a0[4], a1[4];
            ldsm4(a0, offAk);
            ldsm4(a1, offAk + 2048u);
            uint32_t bf[4][4];
            #pragma unroll
            for (int nb = 0; nb < 4; nb++)
                ldsm4(bf[nb], offBk + (uint32_t)nb * 2048u);
            #pragma unroll
            for (int nb = 0; nb < 4; nb++) {
                mma_fp8(acc[0][2 * nb],     a0, bf[nb][0], bf[nb][2]);
                mma_fp8(acc[0][2 * nb + 1], a0, bf[nb][1], bf[nb][3]);
                mma_fp8(acc[1][2 * nb],     a1, bf[nb][0], bf[nb][2]);
                mma_fp8(acc[1][2 * nb + 1], a1, bf[nb][1], bf[nb][3]);
            }
        }
    }

    // epilogue: flag dot_fp8 > 0.4375*(h_i+h_j) - 0.285 (permuted positions)
    const bool diag = (ti == tj);
    const int g = lane >> 2, t4 = lane & 3;
    #pragma unroll
    for (int ma = 0; ma < 2; ma++)
        #pragma unroll
        for (int nf = 0; nf < 8; nf++)
            #pragma unroll
            for (int r = 0; r < 4; r++) {
                float v = acc[ma][nf][r];
                float thr = hI[wy * 32 + ma * 16 + g + (r >> 1) * 8] +
                            thrJ[wx * 64 + nf * 8 + t4 * 2 + (r & 1)];
                if (v > thr) {
                    int pi = iBase + wy * 32 + ma * 16 + g + (r >> 1) * 8;
                    int pj = jBase + wx * 64 + nf * 8 + t4 * 2 + (r & 1);
                    if (!diag || pj > pi) {
                        unsigned pos = atomicAdd(&g_cand_n, 1u);
                        if (pos < CAP)
                            g_cand[pos] = ((unsigned)pi << 14) | (unsigned)pj;
                    }
                }
            }
}

// ---------------- kernel 4: exact fp32 fixup (parallel, 64 blocks) ---------
__global__ void fixup_kernel(const float* __restrict__ classes,
                             const int* __restrict__ ids,
                             const float* __restrict__ emb) {
    unsigned n = g_cand_n;
    if (n > CAP) n = CAP;
    int warpId = (blockIdx.x * blockDim.x + threadIdx.x) >> 5;
    int lane = threadIdx.x & 31;
    int nWarps = (gridDim.x * blockDim.x) >> 5;
    for (unsigned c = warpId; c < n; c += nWarps) {
        unsigned pk = g_cand[c];
        int pi = pk >> 14, pj = pk & 16383;
        int i = g_perm[pi], j = g_perm[pj];
        if (i < 0 || j < 0) continue;
        float inv_i = g_inv[i], inv_j = g_inv[j];
        float s = 0.0f;
        #pragma unroll 4
        for (int k = lane; k < D; k += 32) {
            float a = emb[(size_t)i * D + k] * inv_i;
            float b = emb[(size_t)j * D + k] * inv_j;
            s += a * b;
        }
        #pragma unroll
        for (int o = 16; o > 0; o >>= 1) s += __shfl_down_sync(0xffffffff, s, o);
        if (lane == 0) {
            if (ids[i] != ids[j] && classes[i] == classes[j]) {
                float d2 = fmaxf(g_sq[i] + g_sq[j] - 2.0f * s, 0.0f);
                float term = fmaxf(0.0f, MARGIN - d2);
                if (term > 0.0f) atomicAdd(&g_hinge, term);
            }
        }
    }
}

// ---------------- kernel 5: BCE partials (overlapped on side stream) -------
__global__ void bce_kernel(const float* __restrict__ outputs,
                           const float* __restrict__ classes) {
    float s = 0.0f;
    for (int i = blockIdx.x * blockDim.x + threadIdx.x; i < B;
         i += gridDim.x * blockDim.x) {
        float o = outputs[i], cl = classes[i];
        s += fmaxf(o, 0.0f) - o * cl + log1pf(expf(-fabsf(o)));
    }
    __shared__ float red[256];
    red[threadIdx.x] = s;
    __syncthreads();
    #pragma unroll
    for (int k = 128; k > 0; k >>= 1) {
        if (threadIdx.x < k) red[threadIdx.x] += red[threadIdx.x + k];
        __syncthreads();
    }
    if (threadIdx.x == 0) g_bce[blockIdx.x] = red[0];
}

// ---------------- kernel 6: final deterministic reduce ----------------
__global__ void final_kernel(float* __restrict__ out) {
    int t = threadIdx.x;  // 256
    __shared__ float redP[256];
    float sp = 0.0f;
    for (int i = t; i < NUM_IDS; i += 256) sp += g_pull[i];
    redP[t] = sp;
    __syncthreads();
    #pragma unroll
    for (int k = 128; k > 0; k >>= 1) {
        if (t < k) redP[t] += redP[t + k];
        __syncthreads();
    }
    if (t == 0) {
        float bsum = 0.0f;
        #pragma unroll
        for (int i = 0; i < BCE_BLOCKS; i++) bsum += g_bce[i];
        float l = 0.5f * redP[0] + g_hinge;
        out[0] = bsum / (float)B + ALPHA * l;
    }
}

// ---------------------------------------------------------------------------
extern "C" void kernel_launch(void* const* d_in, const int* in_sizes, int n_in,
                              void* d_out, int out_size) {
    const float* outputs = (const float*)d_in[0];
    const float* classes = (const float*)d_in[1];
    const float* emb     = (const float*)d_in[2];
    const int*   ids     = (const int*)d_in[3];
    float* out = (float*)d_out;

    static cudaStream_t s1 = nullptr;
    static cudaEvent_t ev0 = nullptr, evA = nullptr, evB = nullptr;
    if (s1 == nullptr) {
        cudaStreamCreateWithFlags(&s1, cudaStreamNonBlocking);
        cudaEventCreateWithFlags(&ev0, cudaEventDisableTiming);
        cudaEventCreateWithFlags(&evA, cudaEventDisableTiming);
        cudaEventCreateWithFlags(&evB, cudaEventDisableTiming);
        cudaFuncSetAttribute(gram_kernel,
                             cudaFuncAttributeMaxDynamicSharedMemorySize,
                             SMEM_GRAM);
    }

    // fork immediately: BCE depends only on inputs
    cudaEventRecord(ev0, 0);
    cudaStreamWaitEvent(s1, ev0, 0);
    bce_kernel<<<BCE_BLOCKS, 256, 0, s1>>>(outputs, classes);

    partition_kernel<<<1, 1024>>>(classes);
    normalize_kernel<<<B / 2, 256>>>(emb);

    // pull on s1 (needs normalize results), concurrent with gram
    cudaEventRecord(evA, 0);
    cudaStreamWaitEvent(s1, evA, 0);
    pull_kernel<<<NUM_IDS, 256, 0, s1>>>(classes, ids, emb);
    cudaEventRecord(evB, s1);

    gram_kernel<<<dim3(TRI_MAX, 2), 256, SMEM_GRAM>>>();
    fixup_kernel<<<64, 256>>>(classes, ids, emb);

    cudaStreamWaitEvent(0, evB, 0);
    final_kernel<<<1, 256>>>(out);
}